// round 1
// baseline (speedup 1.0000x reference)
#include <cuda_runtime.h>
#include <math.h>

#define NTOK 2048
#define NB 4
#define DDIM 512
#define D1 1024
#define EDIM 512
#define ROWS (NB * NTOK)   // 8192
#define GAMMA_F 0.999f

// ---------------- scratch (device globals: allocation-free) ----------------
__device__ float g_xn[ROWS * DDIM];
__device__ float g_u [ROWS * D1];
__device__ float g_v [ROWS * D1];
__device__ float g_y [ROWS * D1];
__device__ float g_arr[NTOK * D1];
__device__ float g_h [NTOK * EDIM];
__device__ float g_act[NTOK * EDIM];

// ---------------- sRMS norm (+ optional ReLU) ----------------
// dim must be 512: 128 threads, one float4 each.
template <bool RELU>
__global__ void srms_kernel(const float* __restrict__ in, float* __restrict__ out) {
    int row = blockIdx.x;
    const float4* ip = (const float4*)(in + (size_t)row * 512);
    float4* op = (float4*)(out + (size_t)row * 512);
    int tid = threadIdx.x;                    // 0..127
    float4 val = ip[tid];
    float ss = val.x * val.x + val.y * val.y + val.z * val.z + val.w * val.w;
    #pragma unroll
    for (int o = 16; o > 0; o >>= 1) ss += __shfl_xor_sync(0xffffffffu, ss, o);
    __shared__ float wsum[4];
    if ((tid & 31) == 0) wsum[tid >> 5] = ss;
    __syncthreads();
    float tot = wsum[0] + wsum[1] + wsum[2] + wsum[3];
    float inv = 1.0f / (sqrtf(tot * (1.0f / 512.0f)) + 1e-8f);
    float4 r;
    r.x = val.x * inv; r.y = val.y * inv; r.z = val.z * inv; r.w = val.w * inv;
    if (RELU) {
        r.x = fmaxf(r.x, 0.0f); r.y = fmaxf(r.y, 0.0f);
        r.z = fmaxf(r.z, 0.0f); r.w = fmaxf(r.w, 0.0f);
    }
    op[tid] = r;
}

// ---------------- position embedding: h0[t,e] = t*Wp[e] + bp[e] ----------------
__global__ void coef0_kernel(const float* __restrict__ Wp, const float* __restrict__ bp,
                             float* __restrict__ out) {
    int t = blockIdx.x;
    int e = threadIdx.x;       // 512 threads
    out[(size_t)t * EDIM + e] = (float)t * Wp[e] + bp[e];
}

// ---------------- generic 128x128x8 SGEMM, fused epilogues ----------------
// C[M,N] = A[M,K] @ W[K,N] + bias   (M%128==0, N%128==0, K%8==0)
// EPI: 0 = none, 1 = silu, 2 = decay (row factor gamma^m, row 0 -> 1), 3 = +res
template <int EPI>
__global__ void sgemm_kernel(const float* __restrict__ A, const float* __restrict__ W,
                             const float* __restrict__ bias, const float* __restrict__ res,
                             float* __restrict__ C, int M, int N, int K) {
    __shared__ float As[8][128];
    __shared__ float Bs[8][128];
    int tid = threadIdx.x;                     // 256
    int n0 = blockIdx.x * 128;
    int m0 = blockIdx.y * 128;

    int arow = tid >> 1, aseg = tid & 1;       // A tile: 128 rows x 8 cols
    int brow = tid >> 5, bcol = tid & 31;      // B tile: 8 rows x 128 cols
    const float* Aptr = A + (size_t)(m0 + arow) * K + aseg * 4;
    const float* Wptr = W + (size_t)brow * N + n0 + bcol * 4;

    int ty = tid >> 4, tx = tid & 15;          // 16x16 compute grid
    float acc[8][8];
    #pragma unroll
    for (int i = 0; i < 8; i++)
        #pragma unroll
        for (int j = 0; j < 8; j++) acc[i][j] = 0.0f;

    for (int k0 = 0; k0 < K; k0 += 8) {
        float4 av = *(const float4*)(Aptr + k0);
        float4 bv = *(const float4*)(Wptr + (size_t)k0 * N);
        __syncthreads();
        As[aseg * 4 + 0][arow] = av.x;
        As[aseg * 4 + 1][arow] = av.y;
        As[aseg * 4 + 2][arow] = av.z;
        As[aseg * 4 + 3][arow] = av.w;
        *(float4*)(&Bs[brow][bcol * 4]) = bv;
        __syncthreads();
        #pragma unroll
        for (int k = 0; k < 8; k++) {
            float ra[8], rb[8];
            *(float4*)(ra)     = *(const float4*)(&As[k][ty * 4]);
            *(float4*)(ra + 4) = *(const float4*)(&As[k][64 + ty * 4]);
            *(float4*)(rb)     = *(const float4*)(&Bs[k][tx * 4]);
            *(float4*)(rb + 4) = *(const float4*)(&Bs[k][64 + tx * 4]);
            #pragma unroll
            for (int i = 0; i < 8; i++)
                #pragma unroll
                for (int j = 0; j < 8; j++)
                    acc[i][j] += ra[i] * rb[j];
        }
    }

    float lg = logf(GAMMA_F);
    #pragma unroll
    for (int i = 0; i < 8; i++) {
        int m = m0 + ((i < 4) ? (ty * 4 + i) : (64 + ty * 4 + i - 4));
        float dec = 1.0f;
        if (EPI == 2) dec = (m == 0) ? 1.0f : expf((float)m * lg);
        #pragma unroll
        for (int half = 0; half < 2; half++) {
            int n_base = n0 + half * 64 + tx * 4;
            float4 o;
            float* po = &o.x;
            #pragma unroll
            for (int j = 0; j < 4; j++) {
                int n = n_base + j;
                float vacc = acc[i][half * 4 + j] + bias[n];
                if (EPI == 1) vacc = vacc / (1.0f + expf(-vacc));
                if (EPI == 2) vacc *= dec;
                if (EPI == 3) vacc += res[(size_t)m * N + n];
                po[j] = vacc;
            }
            *(float4*)(C + (size_t)m * N + n_base) = o;
        }
    }
}

// ---------------- causal depthwise Toeplitz conv + gate ----------------
// y[b,t,c] = u[b,t,c] * sum_{r=0}^{t} arr[r,c] * v[b,t-r,c]
// 64 t x 64 c tile per block; 256 threads; 4x4 microtile; sliding v window.
__global__ void conv_kernel(const float* __restrict__ v, const float* __restrict__ arr,
                            const float* __restrict__ u, float* __restrict__ y) {
    __shared__ float a_s[64][64];
    __shared__ float v_s[128][64];
    int b = blockIdx.z;
    int c0 = blockIdx.y * 64;
    int iblk = (gridDim.x - 1) - blockIdx.x;   // heaviest tiles first
    int t0 = iblk * 64;
    int tid = threadIdx.x;                     // 256
    int tx = tid & 15;                         // c group
    int ty = tid >> 4;                         // t group

    float acc[4][4];
    #pragma unroll
    for (int i = 0; i < 4; i++)
        #pragma unroll
        for (int j = 0; j < 4; j++) acc[i][j] = 0.0f;

    const float* vb = v + (size_t)b * NTOK * D1;

    for (int jb = 0; jb <= iblk; jb++) {
        __syncthreads();
        // load a chunk: rows jb*64..+63, cols c0..c0+63
        #pragma unroll
        for (int it = 0; it < 4; it++) {
            int idx = it * 256 + tid;          // 0..1023
            int rq = idx >> 4;
            int cseg = idx & 15;
            float4 val = *(const float4*)(arr + (size_t)(jb * 64 + rq) * D1 + c0 + cseg * 4);
            *(float4*)(&a_s[rq][cseg * 4]) = val;
        }
        // load v window: global rows gbase..gbase+127 (zero-padded => causality)
        int gbase = t0 - jb * 64 - 63;
        #pragma unroll
        for (int it = 0; it < 8; it++) {
            int idx = it * 256 + tid;          // 0..2047
            int rl = idx >> 4;
            int cseg = idx & 15;
            int g = gbase + rl;
            float4 val = make_float4(0.0f, 0.0f, 0.0f, 0.0f);
            if (g >= 0 && g < NTOK)
                val = *(const float4*)(vb + (size_t)g * D1 + c0 + cseg * 4);
            *(float4*)(&v_s[rl][cseg * 4]) = val;
        }
        __syncthreads();

        // register sliding window: w[i] = v_s[ty*4 + i + 63 - q]
        float4 w[4];
        #pragma unroll
        for (int i = 0; i < 4; i++)
            w[i] = *(const float4*)(&v_s[ty * 4 + i + 63][tx * 4]);

        #pragma unroll
        for (int q = 0; q < 64; q++) {
            float4 av = *(const float4*)(&a_s[q][tx * 4]);
            #pragma unroll
            for (int i = 0; i < 4; i++) {
                acc[i][0] += av.x * w[i].x;
                acc[i][1] += av.y * w[i].y;
                acc[i][2] += av.z * w[i].z;
                acc[i][3] += av.w * w[i].w;
            }
            if (q < 63) {
                #pragma unroll
                for (int i = 3; i > 0; i--) w[i] = w[i - 1];
                w[0] = *(const float4*)(&v_s[ty * 4 + 62 - q][tx * 4]);
            }
        }
    }

    // epilogue: gate with u, write y
    #pragma unroll
    for (int i = 0; i < 4; i++) {
        int t = t0 + ty * 4 + i;
        size_t off = ((size_t)b * NTOK + t) * D1 + c0 + tx * 4;
        float4 uv = *(const float4*)(u + off);
        float4 o;
        o.x = uv.x * acc[i][0];
        o.y = uv.y * acc[i][1];
        o.z = uv.z * acc[i][2];
        o.w = uv.w * acc[i][3];
        *(float4*)(y + off) = o;
    }
}

// ---------------- launch ----------------
extern "C" void kernel_launch(void* const* d_in, const int* in_sizes, int n_in,
                              void* d_out, int out_size) {
    const float* x  = (const float*)d_in[0];
    const float* Wu = (const float*)d_in[1];
    const float* bu = (const float*)d_in[2];
    const float* Wv = (const float*)d_in[3];
    const float* bv = (const float*)d_in[4];
    const float* Wo = (const float*)d_in[5];
    const float* bo = (const float*)d_in[6];
    const float* Wp = (const float*)d_in[7];
    const float* bp = (const float*)d_in[8];
    const float* W1 = (const float*)d_in[9];
    const float* b1 = (const float*)d_in[10];
    const float* W2 = (const float*)d_in[11];
    const float* b2 = (const float*)d_in[12];
    const float* W3 = (const float*)d_in[13];
    const float* b3 = (const float*)d_in[14];
    const float* Wz = (const float*)d_in[15];
    const float* bz = (const float*)d_in[16];
    float* out = (float*)d_out;

    float *xn, *u, *v, *y, *arr, *h, *act;
    cudaGetSymbolAddress((void**)&xn,  g_xn);
    cudaGetSymbolAddress((void**)&u,   g_u);
    cudaGetSymbolAddress((void**)&v,   g_v);
    cudaGetSymbolAddress((void**)&y,   g_y);
    cudaGetSymbolAddress((void**)&arr, g_arr);
    cudaGetSymbolAddress((void**)&h,   g_h);
    cudaGetSymbolAddress((void**)&act, g_act);

    // main path norm
    srms_kernel<false><<<ROWS, 128>>>(x, xn);

    // u, v projections with SiLU
    sgemm_kernel<1><<<dim3(D1 / 128, ROWS / 128), 256>>>(xn, Wu, bu, nullptr, u, ROWS, D1, DDIM);
    sgemm_kernel<1><<<dim3(D1 / 128, ROWS / 128), 256>>>(xn, Wv, bv, nullptr, v, ROWS, D1, DDIM);

    // coefficient MLP (position-only)
    coef0_kernel<<<NTOK, EDIM>>>(Wp, bp, h);
    srms_kernel<true><<<NTOK, 128>>>(h, act);
    sgemm_kernel<0><<<dim3(EDIM / 128, NTOK / 128), 256>>>(act, W1, b1, nullptr, h, NTOK, EDIM, EDIM);
    srms_kernel<true><<<NTOK, 128>>>(h, act);
    sgemm_kernel<0><<<dim3(EDIM / 128, NTOK / 128), 256>>>(act, W2, b2, nullptr, h, NTOK, EDIM, EDIM);
    srms_kernel<true><<<NTOK, 128>>>(h, act);
    sgemm_kernel<0><<<dim3(EDIM / 128, NTOK / 128), 256>>>(act, W3, b3, nullptr, h, NTOK, EDIM, EDIM);
    srms_kernel<true><<<NTOK, 128>>>(h, act);
    // final coef layer with decay applied in epilogue -> arr[r, c]
    sgemm_kernel<2><<<dim3(D1 / 128, NTOK / 128), 256>>>(act, Wz, bz, nullptr, arr, NTOK, D1, EDIM);

    // causal depthwise Toeplitz conv, gated by u
    conv_kernel<<<dim3(NTOK / 64, D1 / 64, NB), 256>>>(v, arr, u, y);

    // output projection + bias + residual
    sgemm_kernel<3><<<dim3(DDIM / 128, ROWS / 128), 256>>>(y, Wo, bo, x, out, ROWS, DDIM, D1);
}

// round 2
// speedup vs baseline: 1.6294x; 1.6294x over previous
#include <cuda_runtime.h>
#include <math.h>
#include <stdint.h>

#define NTOK 2048
#define NB 4
#define DDIM 512
#define D1 1024
#define EDIM 512
#define ROWS (NB * NTOK)   // 8192
#define GAMMA_F 0.999f

// ---------------- scratch (device globals: allocation-free) ----------------
__device__ float g_xn[ROWS * DDIM];
__device__ float g_u [ROWS * D1];
__device__ float g_v [ROWS * D1];
__device__ float g_y [ROWS * D1];
__device__ float g_arr[NTOK * D1];
__device__ float g_h [NTOK * EDIM];
__device__ float g_act[NTOK * EDIM];

// ---------------- helpers ----------------
__device__ __forceinline__ uint32_t to_tf32(float f) {
    uint32_t r;
    asm("cvt.rna.tf32.f32 %0, %1;" : "=r"(r) : "f"(f));
    return r;
}

#define MMA_TF32(ACC, AF, BF)                                                  \
    asm volatile(                                                              \
        "mma.sync.aligned.m16n8k8.row.col.f32.tf32.tf32.f32 "                  \
        "{%0,%1,%2,%3}, {%4,%5,%6,%7}, {%8,%9}, {%0,%1,%2,%3};"               \
        : "+f"((ACC)[0]), "+f"((ACC)[1]), "+f"((ACC)[2]), "+f"((ACC)[3])       \
        : "r"((AF)[0]), "r"((AF)[1]), "r"((AF)[2]), "r"((AF)[3]),              \
          "r"((BF)[0]), "r"((BF)[1]))

#define FFMA2(D, A, B, C)                                                      \
    asm("fma.rn.f32x2 %0, %1, %2, %3;" : "=l"(D) : "l"(A), "l"(B), "l"(C))

// ---------------- sRMS norm (+ optional ReLU), dim = 512 ----------------
template <bool RELU>
__global__ void srms_kernel(const float* __restrict__ in, float* __restrict__ out) {
    int row = blockIdx.x;
    const float4* ip = (const float4*)(in + (size_t)row * 512);
    float4* op = (float4*)(out + (size_t)row * 512);
    int tid = threadIdx.x;                    // 0..127
    float4 val = ip[tid];
    float ss = val.x * val.x + val.y * val.y + val.z * val.z + val.w * val.w;
    #pragma unroll
    for (int o = 16; o > 0; o >>= 1) ss += __shfl_xor_sync(0xffffffffu, ss, o);
    __shared__ float wsum[4];
    if ((tid & 31) == 0) wsum[tid >> 5] = ss;
    __syncthreads();
    float tot = wsum[0] + wsum[1] + wsum[2] + wsum[3];
    float inv = 1.0f / (sqrtf(tot * (1.0f / 512.0f)) + 1e-8f);
    float4 r;
    r.x = val.x * inv; r.y = val.y * inv; r.z = val.z * inv; r.w = val.w * inv;
    if (RELU) {
        r.x = fmaxf(r.x, 0.0f); r.y = fmaxf(r.y, 0.0f);
        r.z = fmaxf(r.z, 0.0f); r.w = fmaxf(r.w, 0.0f);
    }
    op[tid] = r;
}

// ---------------- position embedding: h0[t,e] = t*Wp[e] + bp[e] ----------------
__global__ void coef0_kernel(const float* __restrict__ Wp, const float* __restrict__ bp,
                             float* __restrict__ out) {
    int t = blockIdx.x;
    int e = threadIdx.x;       // 512 threads
    out[(size_t)t * EDIM + e] = (float)t * Wp[e] + bp[e];
}

// ---------------- tf32 tensor-core GEMM, 128x128x32, fused epilogues ----------
// C[M,N] = A[M,K] @ W[K,N] + bias   (M%128==0, N%128==0, K%32==0)
// EPI: 0 = none, 1 = silu, 2 = decay (row factor gamma^m, row 0 -> 1), 3 = +res
template <int EPI>
__global__ void __launch_bounds__(256)
tf32_gemm_kernel(const float* __restrict__ A, const float* __restrict__ W,
                 const float* __restrict__ bias, const float* __restrict__ res,
                 float* __restrict__ C, int M, int N, int K) {
    __shared__ uint32_t As[128][36];   // padded: stride 36 (== 4 mod 32)
    __shared__ uint32_t Bs[32][136];   // padded: stride 136 (== 8 mod 32)

    int tid = threadIdx.x;             // 256
    int n0 = blockIdx.x * 128;
    int m0 = blockIdx.y * 128;
    int warp = tid >> 5, lane = tid & 31;
    int wm = warp >> 2;                // 0..1  (64-row slab)
    int wn = warp & 3;                 // 0..3  (32-col slab)
    int g = lane >> 2, t = lane & 3;

    float acc[4][4][4];
    #pragma unroll
    for (int mt = 0; mt < 4; mt++)
        #pragma unroll
        for (int nt = 0; nt < 4; nt++)
            #pragma unroll
            for (int e = 0; e < 4; e++) acc[mt][nt][e] = 0.0f;

    int ar = tid >> 3;                 // 0..31 (+32*it)
    int ac = (tid & 7) * 4;
    int br = tid >> 5;                 // 0..7  (+8*it)
    int bc = (tid & 31) * 4;

    #pragma unroll 1
    for (int k0 = 0; k0 < K; k0 += 32) {
        float4 asv[4], bsv[4];
        #pragma unroll
        for (int it = 0; it < 4; it++)
            asv[it] = *(const float4*)(A + (size_t)(m0 + ar + 32 * it) * K + k0 + ac);
        #pragma unroll
        for (int it = 0; it < 4; it++)
            bsv[it] = *(const float4*)(W + (size_t)(k0 + br + 8 * it) * N + n0 + bc);
        __syncthreads();
        #pragma unroll
        for (int it = 0; it < 4; it++) {
            uint32_t* p = &As[ar + 32 * it][ac];
            p[0] = to_tf32(asv[it].x); p[1] = to_tf32(asv[it].y);
            p[2] = to_tf32(asv[it].z); p[3] = to_tf32(asv[it].w);
        }
        #pragma unroll
        for (int it = 0; it < 4; it++) {
            uint32_t* p = &Bs[br + 8 * it][bc];
            p[0] = to_tf32(bsv[it].x); p[1] = to_tf32(bsv[it].y);
            p[2] = to_tf32(bsv[it].z); p[3] = to_tf32(bsv[it].w);
        }
        __syncthreads();

        #pragma unroll
        for (int ks = 0; ks < 4; ks++) {
            int kk = ks * 8;
            uint32_t af[4][4], bf[4][2];
            #pragma unroll
            for (int mt = 0; mt < 4; mt++) {
                int row = wm * 64 + mt * 16 + g;
                af[mt][0] = As[row][kk + t];
                af[mt][1] = As[row + 8][kk + t];
                af[mt][2] = As[row][kk + t + 4];
                af[mt][3] = As[row + 8][kk + t + 4];
            }
            #pragma unroll
            for (int nt = 0; nt < 4; nt++) {
                int col = wn * 32 + nt * 8 + g;
                bf[nt][0] = Bs[kk + t][col];
                bf[nt][1] = Bs[kk + t + 4][col];
            }
            #pragma unroll
            for (int mt = 0; mt < 4; mt++)
                #pragma unroll
                for (int nt = 0; nt < 4; nt++)
                    MMA_TF32(acc[mt][nt], af[mt], bf[nt]);
        }
    }

    float lg = logf(GAMMA_F);
    #pragma unroll
    for (int mt = 0; mt < 4; mt++) {
        int mrow0 = m0 + wm * 64 + mt * 16 + g;
        #pragma unroll
        for (int h2 = 0; h2 < 2; h2++) {
            int m = mrow0 + 8 * h2;
            float dec = 1.0f;
            if (EPI == 2) dec = (m == 0) ? 1.0f : expf((float)m * lg);
            #pragma unroll
            for (int nt = 0; nt < 4; nt++) {
                int n = n0 + wn * 32 + nt * 8 + 2 * t;
                float v0 = acc[mt][nt][2 * h2 + 0] + bias[n];
                float v1 = acc[mt][nt][2 * h2 + 1] + bias[n + 1];
                if (EPI == 1) {
                    v0 = v0 / (1.0f + expf(-v0));
                    v1 = v1 / (1.0f + expf(-v1));
                }
                if (EPI == 2) { v0 *= dec; v1 *= dec; }
                if (EPI == 3) {
                    float2 rv = *(const float2*)(res + (size_t)m * N + n);
                    v0 += rv.x; v1 += rv.y;
                }
                float2 o = make_float2(v0, v1);
                *(float2*)(C + (size_t)m * N + n) = o;
            }
        }
    }
}

// ---------------- causal depthwise Toeplitz conv + gate (packed f32x2) -------
// y[b,t,c] = u[b,t,c] * sum_{r=0}^{t} arr[r,c] * v[b,t-r,c]
__global__ void conv_kernel(const float* __restrict__ v, const float* __restrict__ arr,
                            const float* __restrict__ u, float* __restrict__ y) {
    __shared__ float a_s[64][64];
    __shared__ float v_s[128][64];
    int b = blockIdx.z;
    int c0 = blockIdx.y * 64;
    int iblk = (gridDim.x - 1) - blockIdx.x;   // heaviest tiles first
    int t0 = iblk * 64;
    int tid = threadIdx.x;                     // 256
    int tx = tid & 15;                         // c group (4 channels)
    int ty = tid >> 4;                         // t group (4 rows)

    unsigned long long acc2[4][2];
    #pragma unroll
    for (int i = 0; i < 4; i++) { acc2[i][0] = 0ULL; acc2[i][1] = 0ULL; }

    const float* vb = v + (size_t)b * NTOK * D1;

    for (int jb = 0; jb <= iblk; jb++) {
        __syncthreads();
        #pragma unroll
        for (int it = 0; it < 4; it++) {
            int idx = it * 256 + tid;          // 0..1023
            int rq = idx >> 4;
            int cseg = idx & 15;
            float4 val = *(const float4*)(arr + (size_t)(jb * 64 + rq) * D1 + c0 + cseg * 4);
            *(float4*)(&a_s[rq][cseg * 4]) = val;
        }
        int gbase = t0 - jb * 64 - 63;
        #pragma unroll
        for (int it = 0; it < 8; it++) {
            int idx = it * 256 + tid;          // 0..2047
            int rl = idx >> 4;
            int cseg = idx & 15;
            int gg = gbase + rl;
            float4 val = make_float4(0.0f, 0.0f, 0.0f, 0.0f);
            if (gg >= 0 && gg < NTOK)
                val = *(const float4*)(vb + (size_t)gg * D1 + c0 + cseg * 4);
            *(float4*)(&v_s[rl][cseg * 4]) = val;
        }
        __syncthreads();

        // register sliding window (packed pairs)
        unsigned long long w2[4][2];
        #pragma unroll
        for (int i = 0; i < 4; i++) {
            ulonglong2 wv = *(const ulonglong2*)(&v_s[ty * 4 + i + 63][tx * 4]);
            w2[i][0] = wv.x; w2[i][1] = wv.y;
        }

        #pragma unroll
        for (int q = 0; q < 64; q++) {
            ulonglong2 a2 = *(const ulonglong2*)(&a_s[q][tx * 4]);
            #pragma unroll
            for (int i = 0; i < 4; i++) {
                FFMA2(acc2[i][0], a2.x, w2[i][0], acc2[i][0]);
                FFMA2(acc2[i][1], a2.y, w2[i][1], acc2[i][1]);
            }
            if (q < 63) {
                #pragma unroll
                for (int i = 3; i > 0; i--) { w2[i][0] = w2[i - 1][0]; w2[i][1] = w2[i - 1][1]; }
                ulonglong2 wv = *(const ulonglong2*)(&v_s[ty * 4 + 62 - q][tx * 4]);
                w2[0][0] = wv.x; w2[0][1] = wv.y;
            }
        }
    }

    // epilogue: gate with u, write y
    #pragma unroll
    for (int i = 0; i < 4; i++) {
        int t = t0 + ty * 4 + i;
        size_t off = ((size_t)b * NTOK + t) * D1 + c0 + tx * 4;
        float4 uv = *(const float4*)(u + off);
        float2 lo = *(float2*)(&acc2[i][0]);
        float2 hi = *(float2*)(&acc2[i][1]);
        float4 o;
        o.x = uv.x * lo.x;
        o.y = uv.y * lo.y;
        o.z = uv.z * hi.x;
        o.w = uv.w * hi.y;
        *(float4*)(y + off) = o;
    }
}

// ---------------- launch ----------------
extern "C" void kernel_launch(void* const* d_in, const int* in_sizes, int n_in,
                              void* d_out, int out_size) {
    const float* x  = (const float*)d_in[0];
    const float* Wu = (const float*)d_in[1];
    const float* bu = (const float*)d_in[2];
    const float* Wv = (const float*)d_in[3];
    const float* bv = (const float*)d_in[4];
    const float* Wo = (const float*)d_in[5];
    const float* bo = (const float*)d_in[6];
    const float* Wp = (const float*)d_in[7];
    const float* bp = (const float*)d_in[8];
    const float* W1 = (const float*)d_in[9];
    const float* b1 = (const float*)d_in[10];
    const float* W2 = (const float*)d_in[11];
    const float* b2 = (const float*)d_in[12];
    const float* W3 = (const float*)d_in[13];
    const float* b3 = (const float*)d_in[14];
    const float* Wz = (const float*)d_in[15];
    const float* bz = (const float*)d_in[16];
    float* out = (float*)d_out;

    float *xn, *u, *v, *y, *arr, *h, *act;
    cudaGetSymbolAddress((void**)&xn,  g_xn);
    cudaGetSymbolAddress((void**)&u,   g_u);
    cudaGetSymbolAddress((void**)&v,   g_v);
    cudaGetSymbolAddress((void**)&y,   g_y);
    cudaGetSymbolAddress((void**)&arr, g_arr);
    cudaGetSymbolAddress((void**)&h,   g_h);
    cudaGetSymbolAddress((void**)&act, g_act);

    // main path norm
    srms_kernel<false><<<ROWS, 128>>>(x, xn);

    // u, v projections with SiLU (tf32 tensor cores)
    tf32_gemm_kernel<1><<<dim3(D1 / 128, ROWS / 128), 256>>>(xn, Wu, bu, nullptr, u, ROWS, D1, DDIM);
    tf32_gemm_kernel<1><<<dim3(D1 / 128, ROWS / 128), 256>>>(xn, Wv, bv, nullptr, v, ROWS, D1, DDIM);

    // coefficient MLP (position-only)
    coef0_kernel<<<NTOK, EDIM>>>(Wp, bp, h);
    srms_kernel<true><<<NTOK, 128>>>(h, act);
    tf32_gemm_kernel<0><<<dim3(EDIM / 128, NTOK / 128), 256>>>(act, W1, b1, nullptr, h, NTOK, EDIM, EDIM);
    srms_kernel<true><<<NTOK, 128>>>(h, act);
    tf32_gemm_kernel<0><<<dim3(EDIM / 128, NTOK / 128), 256>>>(act, W2, b2, nullptr, h, NTOK, EDIM, EDIM);
    srms_kernel<true><<<NTOK, 128>>>(h, act);
    tf32_gemm_kernel<0><<<dim3(EDIM / 128, NTOK / 128), 256>>>(act, W3, b3, nullptr, h, NTOK, EDIM, EDIM);
    srms_kernel<true><<<NTOK, 128>>>(h, act);
    // final coef layer with decay applied in epilogue -> arr[r, c]
    tf32_gemm_kernel<2><<<dim3(D1 / 128, NTOK / 128), 256>>>(act, Wz, bz, nullptr, arr, NTOK, D1, EDIM);

    // causal depthwise Toeplitz conv, gated by u (packed f32x2 FMA)
    conv_kernel<<<dim3(NTOK / 64, D1 / 64, NB), 256>>>(v, arr, u, y);

    // output projection + bias + residual
    tf32_gemm_kernel<3><<<dim3(DDIM / 128, ROWS / 128), 256>>>(y, Wo, bo, x, out, ROWS, DDIM, D1);
}

// round 3
// speedup vs baseline: 1.8225x; 1.1185x over previous
#include <cuda_runtime.h>
#include <math.h>
#include <stdint.h>

#define NTOK 2048
#define NB 4
#define DDIM 512
#define D1 1024
#define EDIM 512
#define ROWS (NB * NTOK)   // 8192
#define GAMMA_F 0.999f

// ---------------- scratch (device globals: allocation-free) ----------------
__device__ float g_xn[ROWS * DDIM];
__device__ float g_u [ROWS * D1];
__device__ float g_v [ROWS * D1];
__device__ float g_y [ROWS * D1];
__device__ float g_arr[NTOK * D1];
__device__ float g_h [NTOK * EDIM];
__device__ float g_act[NTOK * EDIM];

// ---------------- helpers ----------------
__device__ __forceinline__ uint32_t to_tf32(float f) {
    uint32_t r;
    asm("cvt.rna.tf32.f32 %0, %1;" : "=r"(r) : "f"(f));
    return r;
}

#define MMA_TF32(ACC, AF, BF)                                                  \
    asm volatile(                                                              \
        "mma.sync.aligned.m16n8k8.row.col.f32.tf32.tf32.f32 "                  \
        "{%0,%1,%2,%3}, {%4,%5,%6,%7}, {%8,%9}, {%0,%1,%2,%3};"               \
        : "+f"((ACC)[0]), "+f"((ACC)[1]), "+f"((ACC)[2]), "+f"((ACC)[3])       \
        : "r"((AF)[0]), "r"((AF)[1]), "r"((AF)[2]), "r"((AF)[3]),              \
          "r"((BF)[0]), "r"((BF)[1]))

#define FFMA2(D, A, B, C)                                                      \
    asm("fma.rn.f32x2 %0, %1, %2, %3;" : "=l"(D) : "l"(A), "l"(B), "l"(C))

// ---------------- sRMS norm (+ optional ReLU), dim = 512 ----------------
template <bool RELU>
__global__ void srms_kernel(const float* __restrict__ in, float* __restrict__ out) {
    int row = blockIdx.x;
    const float4* ip = (const float4*)(in + (size_t)row * 512);
    float4* op = (float4*)(out + (size_t)row * 512);
    int tid = threadIdx.x;                    // 0..127
    float4 val = ip[tid];
    float ss = val.x * val.x + val.y * val.y + val.z * val.z + val.w * val.w;
    #pragma unroll
    for (int o = 16; o > 0; o >>= 1) ss += __shfl_xor_sync(0xffffffffu, ss, o);
    __shared__ float wsum[4];
    if ((tid & 31) == 0) wsum[tid >> 5] = ss;
    __syncthreads();
    float tot = wsum[0] + wsum[1] + wsum[2] + wsum[3];
    float inv = 1.0f / (sqrtf(tot * (1.0f / 512.0f)) + 1e-8f);
    float4 r;
    r.x = val.x * inv; r.y = val.y * inv; r.z = val.z * inv; r.w = val.w * inv;
    if (RELU) {
        r.x = fmaxf(r.x, 0.0f); r.y = fmaxf(r.y, 0.0f);
        r.z = fmaxf(r.z, 0.0f); r.w = fmaxf(r.w, 0.0f);
    }
    op[tid] = r;
}

// ---------------- position embedding: h0[t,e] = t*Wp[e] + bp[e] ----------------
__global__ void coef0_kernel(const float* __restrict__ Wp, const float* __restrict__ bp,
                             float* __restrict__ out) {
    int t = blockIdx.x;
    int e = threadIdx.x;       // 512 threads
    out[(size_t)t * EDIM + e] = (float)t * Wp[e] + bp[e];
}

// ---------------- tf32 tensor-core GEMM, 128x128x32, pipelined 2-stage -------
// C[M,N] = A[M,K] @ W[K,N] + bias   (M%128==0, N%128==0, K%32==0)
// EPI: 0 = none, 1 = silu, 2 = decay (row factor gamma^m, row 0 -> 1), 3 = +res
#define AS_SZ (128 * 36)
#define BS_SZ (32 * 136)
#define GEMM_SMEM ((2 * (AS_SZ + BS_SZ)) * 4)

template <int EPI>
__global__ void __launch_bounds__(256)
tf32_gemm_kernel(const float* __restrict__ A, const float* __restrict__ W,
                 const float* __restrict__ bias, const float* __restrict__ res,
                 float* __restrict__ C, int M, int N, int K) {
    extern __shared__ uint32_t sm[];

    int tid = threadIdx.x;             // 256
    int n0 = blockIdx.x * 128;
    int m0 = blockIdx.y * 128;
    int warp = tid >> 5, lane = tid & 31;
    int wm = warp >> 2;                // 0..1  (64-row slab)
    int wn = warp & 3;                 // 0..3  (32-col slab)
    int g = lane >> 2, t = lane & 3;

    float acc[4][4][4];
    #pragma unroll
    for (int mt = 0; mt < 4; mt++)
        #pragma unroll
        for (int nt = 0; nt < 4; nt++)
            #pragma unroll
            for (int e = 0; e < 4; e++) acc[mt][nt][e] = 0.0f;

    int ar = tid >> 3;                 // 0..31 (+32*it)
    int ac = (tid & 7) * 4;
    int br = tid >> 5;                 // 0..7  (+8*it)
    int bc = (tid & 31) * 4;

    // prefetch chunk 0
    float4 asv[4], bsv[4];
    #pragma unroll
    for (int it = 0; it < 4; it++)
        asv[it] = *(const float4*)(A + (size_t)(m0 + ar + 32 * it) * K + ac);
    #pragma unroll
    for (int it = 0; it < 4; it++)
        bsv[it] = *(const float4*)(W + (size_t)(br + 8 * it) * N + n0 + bc);

    #pragma unroll 1
    for (int k0 = 0; k0 < K; k0 += 32) {
        int st = (k0 >> 5) & 1;
        uint32_t* As = sm + st * AS_SZ;                 // [128][36]
        uint32_t* Bs = sm + 2 * AS_SZ + st * BS_SZ;     // [32][136]

        // store current chunk (with tf32 convert)
        #pragma unroll
        for (int it = 0; it < 4; it++) {
            uint32_t* p = &As[(ar + 32 * it) * 36 + ac];
            p[0] = to_tf32(asv[it].x); p[1] = to_tf32(asv[it].y);
            p[2] = to_tf32(asv[it].z); p[3] = to_tf32(asv[it].w);
        }
        #pragma unroll
        for (int it = 0; it < 4; it++) {
            uint32_t* p = &Bs[(br + 8 * it) * 136 + bc];
            p[0] = to_tf32(bsv[it].x); p[1] = to_tf32(bsv[it].y);
            p[2] = to_tf32(bsv[it].z); p[3] = to_tf32(bsv[it].w);
        }
        __syncthreads();

        // prefetch next chunk while MMAs run
        int kn = k0 + 32;
        if (kn < K) {
            #pragma unroll
            for (int it = 0; it < 4; it++)
                asv[it] = *(const float4*)(A + (size_t)(m0 + ar + 32 * it) * K + kn + ac);
            #pragma unroll
            for (int it = 0; it < 4; it++)
                bsv[it] = *(const float4*)(W + (size_t)(kn + br + 8 * it) * N + n0 + bc);
        }

        #pragma unroll
        for (int ks = 0; ks < 4; ks++) {
            int kk = ks * 8;
            uint32_t af[4][4], bf[4][2];
            #pragma unroll
            for (int mt = 0; mt < 4; mt++) {
                int row = wm * 64 + mt * 16 + g;
                af[mt][0] = As[row * 36 + kk + t];
                af[mt][1] = As[(row + 8) * 36 + kk + t];
                af[mt][2] = As[row * 36 + kk + t + 4];
                af[mt][3] = As[(row + 8) * 36 + kk + t + 4];
            }
            #pragma unroll
            for (int nt = 0; nt < 4; nt++) {
                int col = wn * 32 + nt * 8 + g;
                bf[nt][0] = Bs[(kk + t) * 136 + col];
                bf[nt][1] = Bs[(kk + t + 4) * 136 + col];
            }
            #pragma unroll
            for (int mt = 0; mt < 4; mt++)
                #pragma unroll
                for (int nt = 0; nt < 4; nt++)
                    MMA_TF32(acc[mt][nt], af[mt], bf[nt]);
        }
    }

    float lg = logf(GAMMA_F);
    #pragma unroll
    for (int mt = 0; mt < 4; mt++) {
        int mrow0 = m0 + wm * 64 + mt * 16 + g;
        #pragma unroll
        for (int h2 = 0; h2 < 2; h2++) {
            int m = mrow0 + 8 * h2;
            float dec = 1.0f;
            if (EPI == 2) dec = (m == 0) ? 1.0f : expf((float)m * lg);
            #pragma unroll
            for (int nt = 0; nt < 4; nt++) {
                int n = n0 + wn * 32 + nt * 8 + 2 * t;
                float v0 = acc[mt][nt][2 * h2 + 0] + bias[n];
                float v1 = acc[mt][nt][2 * h2 + 1] + bias[n + 1];
                if (EPI == 1) {
                    v0 = v0 / (1.0f + expf(-v0));
                    v1 = v1 / (1.0f + expf(-v1));
                }
                if (EPI == 2) { v0 *= dec; v1 *= dec; }
                if (EPI == 3) {
                    float2 rv = *(const float2*)(res + (size_t)m * N + n);
                    v0 += rv.x; v1 += rv.y;
                }
                float2 o = make_float2(v0, v1);
                *(float2*)(C + (size_t)m * N + n) = o;
            }
        }
    }
}

// ---------------- causal depthwise Toeplitz conv + gate (packed f32x2) -------
// y[b,t,c] = u[b,t,c] * sum_{r=0}^{t} arr[r,c] * v[b,t-r,c]
// 128 t x 64 c tile; 256 threads; thread = 8 rows x 4 channels (fma-bound).
#define CONV_SMEM ((64 * 64 + 192 * 64) * 4)

__global__ void __launch_bounds__(256)
conv_kernel(const float* __restrict__ v, const float* __restrict__ arr,
            const float* __restrict__ u, float* __restrict__ y) {
    extern __shared__ float cs[];
    float* a_s = cs;              // [64][64]
    float* v_s = cs + 64 * 64;    // [192][64]

    int b = blockIdx.z;
    int c0 = blockIdx.y * 64;
    int iblk = (gridDim.x - 1) - blockIdx.x;   // heaviest tiles first
    int t0 = iblk * 128;
    int tid = threadIdx.x;                     // 256
    int tx = tid & 15;                         // c group (4 channels)
    int ty = tid >> 4;                         // t group (8 rows)

    unsigned long long acc2[8][2];
    #pragma unroll
    for (int i = 0; i < 8; i++) { acc2[i][0] = 0ULL; acc2[i][1] = 0ULL; }

    const float* vb = v + (size_t)b * NTOK * D1;
    int nch = 2 * iblk + 2;

    for (int jb = 0; jb < nch; jb++) {
        __syncthreads();
        // a chunk: rows jb*64..+63, cols c0..c0+63
        #pragma unroll
        for (int it = 0; it < 4; it++) {
            int idx = it * 256 + tid;          // 0..1023
            int rq = idx >> 4;
            int cseg = idx & 15;
            float4 val = *(const float4*)(arr + (size_t)(jb * 64 + rq) * D1 + c0 + cseg * 4);
            *(float4*)(&a_s[rq * 64 + cseg * 4]) = val;
        }
        // v window: 192 rows, global rows gbase..gbase+191 (zero-pad => causality)
        int gbase = t0 - jb * 64 - 63;
        #pragma unroll
        for (int it = 0; it < 12; it++) {
            int idx = it * 256 + tid;          // 0..3071
            int rl = idx >> 4;
            int cseg = idx & 15;
            int gg = gbase + rl;
            float4 val = make_float4(0.0f, 0.0f, 0.0f, 0.0f);
            if (gg >= 0 && gg < NTOK)
                val = *(const float4*)(vb + (size_t)gg * D1 + c0 + cseg * 4);
            *(float4*)(&v_s[rl * 64 + cseg * 4]) = val;
        }
        __syncthreads();

        // register sliding window: w2[i] ~ v_s[63 + ty*8 + i - q]
        unsigned long long w2[8][2];
        #pragma unroll
        for (int i = 0; i < 8; i++) {
            ulonglong2 wv = *(const ulonglong2*)(&v_s[(63 + ty * 8 + i) * 64 + tx * 4]);
            w2[i][0] = wv.x; w2[i][1] = wv.y;
        }

        #pragma unroll 8
        for (int q = 0; q < 64; q++) {
            ulonglong2 a2 = *(const ulonglong2*)(&a_s[q * 64 + tx * 4]);
            #pragma unroll
            for (int i = 0; i < 8; i++) {
                FFMA2(acc2[i][0], a2.x, w2[i][0], acc2[i][0]);
                FFMA2(acc2[i][1], a2.y, w2[i][1], acc2[i][1]);
            }
            if (q < 63) {
                #pragma unroll
                for (int i = 7; i > 0; i--) { w2[i][0] = w2[i - 1][0]; w2[i][1] = w2[i - 1][1]; }
                ulonglong2 wv = *(const ulonglong2*)(&v_s[(62 + ty * 8 - q) * 64 + tx * 4]);
                w2[0][0] = wv.x; w2[0][1] = wv.y;
            }
        }
    }

    // epilogue: gate with u, write y
    #pragma unroll
    for (int i = 0; i < 8; i++) {
        int t = t0 + ty * 8 + i;
        size_t off = ((size_t)b * NTOK + t) * D1 + c0 + tx * 4;
        float4 uv = *(const float4*)(u + off);
        float2 lo = *(float2*)(&acc2[i][0]);
        float2 hi = *(float2*)(&acc2[i][1]);
        float4 o;
        o.x = uv.x * lo.x;
        o.y = uv.y * lo.y;
        o.z = uv.z * hi.x;
        o.w = uv.w * hi.y;
        *(float4*)(y + off) = o;
    }
}

// ---------------- launch ----------------
extern "C" void kernel_launch(void* const* d_in, const int* in_sizes, int n_in,
                              void* d_out, int out_size) {
    const float* x  = (const float*)d_in[0];
    const float* Wu = (const float*)d_in[1];
    const float* bu = (const float*)d_in[2];
    const float* Wv = (const float*)d_in[3];
    const float* bv = (const float*)d_in[4];
    const float* Wo = (const float*)d_in[5];
    const float* bo = (const float*)d_in[6];
    const float* Wp = (const float*)d_in[7];
    const float* bp = (const float*)d_in[8];
    const float* W1 = (const float*)d_in[9];
    const float* b1 = (const float*)d_in[10];
    const float* W2 = (const float*)d_in[11];
    const float* b2 = (const float*)d_in[12];
    const float* W3 = (const float*)d_in[13];
    const float* b3 = (const float*)d_in[14];
    const float* Wz = (const float*)d_in[15];
    const float* bz = (const float*)d_in[16];
    float* out = (float*)d_out;

    float *xn, *u, *v, *y, *arr, *h, *act;
    cudaGetSymbolAddress((void**)&xn,  g_xn);
    cudaGetSymbolAddress((void**)&u,   g_u);
    cudaGetSymbolAddress((void**)&v,   g_v);
    cudaGetSymbolAddress((void**)&y,   g_y);
    cudaGetSymbolAddress((void**)&arr, g_arr);
    cudaGetSymbolAddress((void**)&h,   g_h);
    cudaGetSymbolAddress((void**)&act, g_act);

    // dynamic-smem opt-in (>48KB); idempotent, not a stream op
    cudaFuncSetAttribute(tf32_gemm_kernel<0>, cudaFuncAttributeMaxDynamicSharedMemorySize, GEMM_SMEM);
    cudaFuncSetAttribute(tf32_gemm_kernel<1>, cudaFuncAttributeMaxDynamicSharedMemorySize, GEMM_SMEM);
    cudaFuncSetAttribute(tf32_gemm_kernel<2>, cudaFuncAttributeMaxDynamicSharedMemorySize, GEMM_SMEM);
    cudaFuncSetAttribute(tf32_gemm_kernel<3>, cudaFuncAttributeMaxDynamicSharedMemorySize, GEMM_SMEM);
    cudaFuncSetAttribute(conv_kernel,         cudaFuncAttributeMaxDynamicSharedMemorySize, CONV_SMEM);

    // main path norm
    srms_kernel<false><<<ROWS, 128>>>(x, xn);

    // u, v projections with SiLU (tf32 tensor cores)
    tf32_gemm_kernel<1><<<dim3(D1 / 128, ROWS / 128), 256, GEMM_SMEM>>>(xn, Wu, bu, nullptr, u, ROWS, D1, DDIM);
    tf32_gemm_kernel<1><<<dim3(D1 / 128, ROWS / 128), 256, GEMM_SMEM>>>(xn, Wv, bv, nullptr, v, ROWS, D1, DDIM);

    // coefficient MLP (position-only)
    coef0_kernel<<<NTOK, EDIM>>>(Wp, bp, h);
    srms_kernel<true><<<NTOK, 128>>>(h, act);
    tf32_gemm_kernel<0><<<dim3(EDIM / 128, NTOK / 128), 256, GEMM_SMEM>>>(act, W1, b1, nullptr, h, NTOK, EDIM, EDIM);
    srms_kernel<true><<<NTOK, 128>>>(h, act);
    tf32_gemm_kernel<0><<<dim3(EDIM / 128, NTOK / 128), 256, GEMM_SMEM>>>(act, W2, b2, nullptr, h, NTOK, EDIM, EDIM);
    srms_kernel<true><<<NTOK, 128>>>(h, act);
    tf32_gemm_kernel<0><<<dim3(EDIM / 128, NTOK / 128), 256, GEMM_SMEM>>>(act, W3, b3, nullptr, h, NTOK, EDIM, EDIM);
    srms_kernel<true><<<NTOK, 128>>>(h, act);
    // final coef layer with decay applied in epilogue -> arr[r, c]
    tf32_gemm_kernel<2><<<dim3(D1 / 128, NTOK / 128), 256, GEMM_SMEM>>>(act, Wz, bz, nullptr, arr, NTOK, D1, EDIM);

    // causal depthwise Toeplitz conv, gated by u (packed f32x2 FMA)
    conv_kernel<<<dim3(NTOK / 128, D1 / 64, NB), 256, CONV_SMEM>>>(v, arr, u, y);

    // output projection + bias + residual
    tf32_gemm_kernel<3><<<dim3(DDIM / 128, ROWS / 128), 256, GEMM_SMEM>>>(y, Wo, bo, x, out, ROWS, DDIM, D1);
}